// round 10
// baseline (speedup 1.0000x reference)
#include <cuda_runtime.h>
#include <cstdint>

// Problem constants: B=2, S=2048, D=1024, H=16, dk=64
constexpr int CB  = 2;
constexpr int CS  = 2048;
constexpr int CD  = 1024;
constexpr int CH  = 16;
constexpr int CDK = 64;
constexpr int CBH = CB * CH;

// Scratch (static device globals — no allocation)
__device__ float g_qh[(size_t)CB * CH * CS * CDK];   // [z][s][dk]
__device__ float g_kh[(size_t)CB * CH * CS * CDK];
__device__ float g_vh[(size_t)CB * CH * CS * CDK];
__device__ float g_om[(size_t)CB * CS * CD];         // merged [B,S,D]
__device__ float g_l[(size_t)CBH * CS];              // row sum of exp(s/8)

__device__ __forceinline__ uint32_t f2tf(float f) {
    uint32_t u;
    asm("cvt.rna.tf32.f32 %0, %1;" : "=r"(u) : "f"(f));
    return u;
}

__device__ __forceinline__ void mma8(float* d, const uint32_t* a, const uint32_t* b) {
    asm volatile(
        "mma.sync.aligned.m16n8k8.row.col.f32.tf32.tf32.f32 "
        "{%0,%1,%2,%3}, {%4,%5,%6,%7}, {%8,%9}, {%0,%1,%2,%3};"
        : "+f"(d[0]), "+f"(d[1]), "+f"(d[2]), "+f"(d[3])
        : "r"(a[0]), "r"(a[1]), "r"(a[2]), "r"(a[3]), "r"(b[0]), "r"(b[1]));
}

__device__ __forceinline__ void ldsm_x4(uint32_t* r, uint32_t addr) {
    asm volatile("ldmatrix.sync.aligned.m8n8.x4.shared.b16 {%0,%1,%2,%3}, [%4];"
                 : "=r"(r[0]), "=r"(r[1]), "=r"(r[2]), "=r"(r[3]) : "r"(addr));
}

// Swizzled word offset inside a [rows][16-word] tile.
__device__ __forceinline__ int swz(int row, int col) {
    return row * 16 + ((((col >> 2) ^ ((row >> 1) & 3)) << 2) | (col & 3));
}

__device__ __forceinline__ void sts8(uint32_t* buf, int row, int col,
                                     float4 a, float4 b) {
    uint4 u0 = make_uint4(f2tf(a.x), f2tf(a.y), f2tf(a.z), f2tf(a.w));
    uint4 u1 = make_uint4(f2tf(b.x), f2tf(b.y), f2tf(b.z), f2tf(b.w));
    *(uint4*)&buf[swz(row, col)]     = u0;
    *(uint4*)&buf[swz(row, col + 4)] = u1;
}

// ===========================================================================
// QKV projection: 128x128 tile, BK=16, double buffered, 2 blocks/SM.
// ===========================================================================
__global__ __launch_bounds__(256, 2) void qkv_proj_kernel(
        const float* __restrict__ X, const float* __restrict__ W,
        const float* __restrict__ bias, float* __restrict__ Yh) {
    __shared__ __align__(16) uint32_t As[2][128 * 16];
    __shared__ __align__(16) uint32_t Bs[2][128 * 16];
    const int tid = threadIdx.x, lane = tid & 31, warp = tid >> 5;
    const int m0 = blockIdx.y * 128, n0 = blockIdx.x * 128;
    const int rowL = tid >> 1, colL = (tid & 1) * 8;
    const int wm = (warp >> 2) * 64, wn = (warp & 3) * 32;
    const int a_row = lane & 15,               a_col = (lane >> 4) * 4;
    const int b_row = (lane & 7) + ((lane >> 4) << 3), b_col = ((lane >> 3) & 1) * 4;

    const float* Ap = X + (size_t)(m0 + rowL) * CD + colL;
    const float* Bp = W + (size_t)(n0 + rowL) * CD + colL;

    float4 ra0 = *(const float4*)Ap, ra1 = *(const float4*)(Ap + 4);
    float4 rb0 = *(const float4*)Bp, rb1 = *(const float4*)(Bp + 4);

    float acc[4][4][4] = {};
    int stage = 0;
    sts8(As[0], rowL, colL, ra0, ra1);
    sts8(Bs[0], rowL, colL, rb0, rb1);
    __syncthreads();

    for (int k0 = 0; k0 < CD; k0 += 16) {
        const bool more = (k0 + 16 < CD);
        if (more) {
            ra0 = *(const float4*)(Ap + k0 + 16); ra1 = *(const float4*)(Ap + k0 + 20);
            rb0 = *(const float4*)(Bp + k0 + 16); rb1 = *(const float4*)(Bp + k0 + 20);
        }
        const uint32_t* as = As[stage];
        const uint32_t* bs = Bs[stage];
#pragma unroll
        for (int ks = 0; ks < 16; ks += 8) {
            uint32_t af[4][4], bq[2][4];
#pragma unroll
            for (int mi = 0; mi < 4; mi++)
                ldsm_x4(af[mi], (uint32_t)__cvta_generic_to_shared(
                            &as[swz(wm + mi * 16 + a_row, ks + a_col)]));
#pragma unroll
            for (int np = 0; np < 2; np++)
                ldsm_x4(bq[np], (uint32_t)__cvta_generic_to_shared(
                            &bs[swz(wn + np * 16 + b_row, ks + b_col)]));
#pragma unroll
            for (int mi = 0; mi < 4; mi++) {
                mma8(acc[mi][0], af[mi], &bq[0][0]);
                mma8(acc[mi][1], af[mi], &bq[0][2]);
                mma8(acc[mi][2], af[mi], &bq[1][0]);
                mma8(acc[mi][3], af[mi], &bq[1][2]);
            }
        }
        if (more) {
            stage ^= 1;
            sts8(As[stage], rowL, colL, ra0, ra1);
            sts8(Bs[stage], rowL, colL, rb0, rb1);
            __syncthreads();
        }
    }
    const int qr = lane >> 2, cb = 2 * (lane & 3);
#pragma unroll
    for (int mi = 0; mi < 4; mi++) {
        const int m  = m0 + wm + mi * 16 + qr;
        const int bb = m >> 11, ss = m & 2047;
#pragma unroll
        for (int ni = 0; ni < 4; ni++) {
            const int n = n0 + wn + ni * 8 + cb;
            const int h = n >> 6, d = n & 63;
            const float b0 = bias[n], b1 = bias[n + 1];
            float* dst = Yh + ((size_t)(bb * CH + h) * CS + ss) * CDK + d;
            *(float2*)dst = make_float2(acc[mi][ni][0] + b0, acc[mi][ni][1] + b1);
            *(float2*)(dst + 8 * CDK) =
                make_float2(acc[mi][ni][2] + b0, acc[mi][ni][3] + b1);
        }
    }
}

// ===========================================================================
// Pass 1: l[row] = sum_j exp(s_ij/8).  j-tile 64, 50KB smem, 2 blocks/SM.
// Warp layout 4m x 2n (32x32 tiles) over the 128x64 S tile.
// ===========================================================================
__global__ __launch_bounds__(256, 2) void stats_kernel(
        const float* __restrict__ qh, const float* __restrict__ kh,
        float* __restrict__ gl) {
    extern __shared__ __align__(16) uint32_t sm[];
    uint32_t* Qs = sm;                    // 4 chunks x 2048
    uint32_t* Ks = sm + 8192;             // 4 chunks x 1024
    float* redL  = (float*)(sm + 12288);  // 256

    const int tid = threadIdx.x, lane = tid & 31, warp = tid >> 5;
    const int z = blockIdx.y, m0 = blockIdx.x * 128;
    const int rowL = tid >> 1, colL = (tid & 1) * 8;
    const int krow = tid & 63, kch = tid >> 6;
    const int wm = (warp >> 1) * 32, wn = (warp & 1) * 32;
    const int a_row = lane & 15,               a_col = (lane >> 4) * 4;
    const int b_row = (lane & 7) + ((lane >> 4) << 3), b_col = ((lane >> 3) & 1) * 4;
    const int qr = lane >> 2;

    const float* Qg = qh + ((size_t)z * CS + m0) * CDK;
    const float* Kg = kh + (size_t)z * CS * CDK;

#pragma unroll
    for (int c = 0; c < 4; c++) {
        const float* s = Qg + (size_t)rowL * CDK + c * 16 + colL;
        sts8(Qs + c * 2048, rowL, colL, *(const float4*)s, *(const float4*)(s + 4));
    }
    float4 kp[4];
    {
        const float* s = Kg + (size_t)krow * CDK + kch * 16;
#pragma unroll
        for (int i = 0; i < 4; i++) kp[i] = *(const float4*)(s + i * 4);
    }
    __syncthreads();

    float lacc[2][2] = {};
    for (int jb = 0; jb < 32; jb++) {
        sts8(Ks + kch * 1024, krow, 0, kp[0], kp[1]);
        sts8(Ks + kch * 1024, krow, 8, kp[2], kp[3]);
        __syncthreads();
        if (jb < 31) {
            const float* s = Kg + (size_t)((jb + 1) * 64 + krow) * CDK + kch * 16;
#pragma unroll
            for (int i = 0; i < 4; i++) kp[i] = *(const float4*)(s + i * 4);
        }

        float acc[2][4][4] = {};
#pragma unroll
        for (int c = 0; c < 4; c++) {
            const uint32_t* as = Qs + c * 2048;
            const uint32_t* bs = Ks + c * 1024;
#pragma unroll
            for (int ks = 0; ks < 16; ks += 8) {
                uint32_t af[2][4], bq[2][4];
#pragma unroll
                for (int mi = 0; mi < 2; mi++)
                    ldsm_x4(af[mi], (uint32_t)__cvta_generic_to_shared(
                                &as[swz(wm + mi * 16 + a_row, ks + a_col)]));
#pragma unroll
                for (int np = 0; np < 2; np++)
                    ldsm_x4(bq[np], (uint32_t)__cvta_generic_to_shared(
                                &bs[swz(wn + np * 16 + b_row, ks + b_col)]));
#pragma unroll
                for (int mi = 0; mi < 2; mi++) {
                    mma8(acc[mi][0], af[mi], &bq[0][0]);
                    mma8(acc[mi][1], af[mi], &bq[0][2]);
                    mma8(acc[mi][2], af[mi], &bq[1][0]);
                    mma8(acc[mi][3], af[mi], &bq[1][2]);
                }
            }
        }
#pragma unroll
        for (int mi = 0; mi < 2; mi++)
#pragma unroll
            for (int ni = 0; ni < 4; ni++) {
                lacc[mi][0] += __expf(acc[mi][ni][0] * 0.125f) +
                               __expf(acc[mi][ni][1] * 0.125f);
                lacc[mi][1] += __expf(acc[mi][ni][2] * 0.125f) +
                               __expf(acc[mi][ni][3] * 0.125f);
            }
        __syncthreads();   // Ks reads done before next STS
    }
#pragma unroll
    for (int mi = 0; mi < 2; mi++)
#pragma unroll
        for (int h = 0; h < 2; h++) {
            float v = lacc[mi][h];
            v += __shfl_xor_sync(~0u, v, 1);
            v += __shfl_xor_sync(~0u, v, 2);
            if ((lane & 3) == 0)
                redL[(wm + mi * 16 + qr + 8 * h) * 2 + (warp & 1)] = v;
        }
    __syncthreads();
    if (tid < 128)
        gl[(size_t)z * CS + m0 + tid] = redL[tid * 2] + redL[tid * 2 + 1];
}

// ===========================================================================
// Pass 2: recompute S (128x64 tiles), write normalized attn once, O += P@V.
// ~101KB smem -> 2 blocks/SM. 2 syncs/jb; K/V prefetched under MMA.
// ===========================================================================
__global__ __launch_bounds__(256, 2) void fused_pv_kernel(
        const float* __restrict__ qh, const float* __restrict__ kh,
        const float* __restrict__ vh, const float* __restrict__ gl,
        float* __restrict__ attn, float* __restrict__ om) {
    extern __shared__ __align__(16) uint32_t sm[];
    uint32_t* Qs = sm;                    // 4 x 2048 = 8192
    uint32_t* Ks = sm + 8192;             // 4 x 1024 = 4096
    uint32_t* Vs = sm + 12288;            // 64*72    = 4608
    uint32_t* Ps = sm + 16896;            // 4 x 2048 = 8192
    float* iS = (float*)(sm + 25088);     // 128

    const int tid = threadIdx.x, lane = tid & 31, warp = tid >> 5;
    const int z = blockIdx.y, m0 = blockIdx.x * 128;
    const int rowL = tid >> 1, colL = (tid & 1) * 8;
    const int krow = tid & 63, kch = tid >> 6;
    const int vrow = tid & 63, vc0 = (tid >> 6) * 16;
    const int wm = (warp >> 1) * 32, wn = (warp & 1) * 32;
    const int a_row = lane & 15,               a_col = (lane >> 4) * 4;
    const int b_row = (lane & 7) + ((lane >> 4) << 3), b_col = ((lane >> 3) & 1) * 4;
    const int qr = lane >> 2, cb = 2 * (lane & 3);

    const float* Qg = qh + ((size_t)z * CS + m0) * CDK;
    const float* Kg = kh + (size_t)z * CS * CDK;
    const float* Vg = vh + (size_t)z * CS * CDK;
    float* Cattn = attn + (size_t)z * CS * CS;

    // Prologue: Q, K(0), V(0), iS
#pragma unroll
    for (int c = 0; c < 4; c++) {
        const float* s = Qg + (size_t)rowL * CDK + c * 16 + colL;
        sts8(Qs + c * 2048, rowL, colL, *(const float4*)s, *(const float4*)(s + 4));
    }
    {
        const float* s = Kg + (size_t)krow * CDK + kch * 16;
        sts8(Ks + kch * 1024, krow, 0, *(const float4*)s, *(const float4*)(s + 4));
        sts8(Ks + kch * 1024, krow, 8, *(const float4*)(s + 8), *(const float4*)(s + 12));
    }
    {
        const float* s = Vg + (size_t)vrow * CDK + vc0;
#pragma unroll
        for (int i = 0; i < 4; i++) {
            float4 t = *(const float4*)(s + i * 4);
            *(uint4*)&Vs[vrow * 72 + vc0 + i * 4] =
                make_uint4(f2tf(t.x), f2tf(t.y), f2tf(t.z), f2tf(t.w));
        }
    }
    if (tid < 128) iS[tid] = 1.0f / gl[(size_t)z * CS + m0 + tid];
    float acc_o[2][4][4] = {};
    __syncthreads();

    for (int jb = 0; jb < 32; jb++) {
        const int j0 = jb * 64;
        const bool more = (jb < 31);

        // Prefetch next K/V into registers (hidden under S-MMA / PV)
        float4 kp[4], vp[4];
        if (more) {
            const float* s = Kg + (size_t)(j0 + 64 + krow) * CDK + kch * 16;
#pragma unroll
            for (int i = 0; i < 4; i++) kp[i] = *(const float4*)(s + i * 4);
            const float* v = Vg + (size_t)(j0 + 64 + vrow) * CDK + vc0;
#pragma unroll
            for (int i = 0; i < 4; i++) vp[i] = *(const float4*)(v + i * 4);
        }

        // --- S = Q @ K^T (128x64), warp tile 32x32 ---
        float acc[2][4][4] = {};
#pragma unroll
        for (int c = 0; c < 4; c++) {
            const uint32_t* as = Qs + c * 2048;
            const uint32_t* bs = Ks + c * 1024;
#pragma unroll
            for (int ks = 0; ks < 16; ks += 8) {
                uint32_t af[2][4], bq[2][4];
#pragma unroll
                for (int mi = 0; mi < 2; mi++)
                    ldsm_x4(af[mi], (uint32_t)__cvta_generic_to_shared(
                                &as[swz(wm + mi * 16 + a_row, ks + a_col)]));
#pragma unroll
                for (int np = 0; np < 2; np++)
                    ldsm_x4(bq[np], (uint32_t)__cvta_generic_to_shared(
                                &bs[swz(wn + np * 16 + b_row, ks + b_col)]));
#pragma unroll
                for (int mi = 0; mi < 2; mi++) {
                    mma8(acc[mi][0], af[mi], &bq[0][0]);
                    mma8(acc[mi][1], af[mi], &bq[0][2]);
                    mma8(acc[mi][2], af[mi], &bq[1][0]);
                    mma8(acc[mi][3], af[mi], &bq[1][2]);
                }
            }
        }

        // --- P = exp(s/8)/l : streaming store attn + tf32 to Ps ---
#pragma unroll
        for (int mi = 0; mi < 2; mi++) {
            const int r0 = wm + mi * 16 + qr;
            const float i0 = iS[r0], i1 = iS[r0 + 8];
#pragma unroll
            for (int ni = 0; ni < 4; ni++) {
                const int n = wn + ni * 8 + cb;
                const float p0 = __expf(acc[mi][ni][0] * 0.125f) * i0;
                const float p1 = __expf(acc[mi][ni][1] * 0.125f) * i0;
                const float p2 = __expf(acc[mi][ni][2] * 0.125f) * i1;
                const float p3 = __expf(acc[mi][ni][3] * 0.125f) * i1;
                __stcs((float2*)(Cattn + (size_t)(m0 + r0) * CS + j0 + n),
                       make_float2(p0, p1));
                __stcs((float2*)(Cattn + (size_t)(m0 + r0 + 8) * CS + j0 + n),
                       make_float2(p2, p3));
                const int c = n >> 4, cl = n & 15;
                *(uint2*)&Ps[c * 2048 + swz(r0, cl)]     = make_uint2(f2tf(p0), f2tf(p1));
                *(uint2*)&Ps[c * 2048 + swz(r0 + 8, cl)] = make_uint2(f2tf(p2), f2tf(p3));
            }
        }
        __syncthreads();   // A: Ps visible, Ks reads done

        if (more) {
            sts8(Ks + kch * 1024, krow, 0, kp[0], kp[1]);
            sts8(Ks + kch * 1024, krow, 8, kp[2], kp[3]);
        }

        // --- O += P @ V : warp tile 32x32, K=64 ---
#pragma unroll
        for (int kslice = 0; kslice < 8; kslice++) {
            const uint32_t* as = Ps + (kslice >> 1) * 2048;
            const int ks2 = (kslice & 1) * 8;
            uint32_t af[2][4], bf[4][2];
#pragma unroll
            for (int mi = 0; mi < 2; mi++)
                ldsm_x4(af[mi], (uint32_t)__cvta_generic_to_shared(
                            &as[swz(wm + mi * 16 + a_row, ks2 + a_col)]));
            const int kf = kslice * 8 + (lane & 3);
            const int nf = wn + qr;
#pragma unroll
            for (int ni = 0; ni < 4; ni++) {
                bf[ni][0] = Vs[kf * 72 + nf + ni * 8];
                bf[ni][1] = Vs[(kf + 4) * 72 + nf + ni * 8];
            }
#pragma unroll
            for (int mi = 0; mi < 2; mi++)
#pragma unroll
                for (int ni = 0; ni < 4; ni++)
                    mma8(acc_o[mi][ni], af[mi], bf[ni]);
        }
        __syncthreads();   // B: Vs/Ps reads done, Ks STS visible

        if (more) {
#pragma unroll
            for (int i = 0; i < 4; i++)
                *(uint4*)&Vs[vrow * 72 + vc0 + i * 4] =
                    make_uint4(f2tf(vp[i].x), f2tf(vp[i].y),
                               f2tf(vp[i].z), f2tf(vp[i].w));
        }
    }
    // --- O epilogue: merged [B,S,D] ---
    const int bb = z >> 4, h = z & 15;
#pragma unroll
    for (int mi = 0; mi < 2; mi++) {
        const int m = m0 + wm + mi * 16 + qr;
#pragma unroll
        for (int ni = 0; ni < 4; ni++) {
            const int n = wn + ni * 8 + cb;
            float* dst = om + ((size_t)(bb * CS + m)) * CD + h * 64 + n;
            *(float2*)dst = make_float2(acc_o[mi][ni][0], acc_o[mi][ni][1]);
            *(float2*)(dst + 8 * CD) = make_float2(acc_o[mi][ni][2], acc_o[mi][ni][3]);
        }
    }
}

// ===========================================================================
// Output projection: out = om @ Wo^T + bo. 2 blocks/SM.
// ===========================================================================
__global__ __launch_bounds__(256, 2) void out_proj_kernel(
        const float* __restrict__ OM, const float* __restrict__ W,
        const float* __restrict__ bias, float* __restrict__ Y) {
    __shared__ __align__(16) uint32_t As[2][128 * 16];
    __shared__ __align__(16) uint32_t Bs[2][128 * 16];
    const int tid = threadIdx.x, lane = tid & 31, warp = tid >> 5;
    const int m0 = blockIdx.y * 128, n0 = blockIdx.x * 128;
    const int rowL = tid >> 1, colL = (tid & 1) * 8;
    const int wm = (warp >> 2) * 64, wn = (warp & 3) * 32;
    const int a_row = lane & 15,               a_col = (lane >> 4) * 4;
    const int b_row = (lane & 7) + ((lane >> 4) << 3), b_col = ((lane >> 3) & 1) * 4;

    const float* Ap = OM + (size_t)(m0 + rowL) * CD + colL;
    const float* Bp = W + (size_t)(n0 + rowL) * CD + colL;

    float4 ra0 = *(const float4*)Ap, ra1 = *(const float4*)(Ap + 4);
    float4 rb0 = *(const float4*)Bp, rb1 = *(const float4*)(Bp + 4);

    float acc[4][4][4] = {};
    int stage = 0;
    sts8(As[0], rowL, colL, ra0, ra1);
    sts8(Bs[0], rowL, colL, rb0, rb1);
    __syncthreads();

    for (int k0 = 0; k0 < CD; k0 += 16) {
        const bool more = (k0 + 16 < CD);
        if (more) {
            ra0 = *(const float4*)(Ap + k0 + 16); ra1 = *(const float4*)(Ap + k0 + 20);
            rb0 = *(const float4*)(Bp + k0 + 16); rb1 = *(const float4*)(Bp + k0 + 20);
        }
        const uint32_t* as = As[stage];
        const uint32_t* bs = Bs[stage];
#pragma unroll
        for (int ks = 0; ks < 16; ks += 8) {
            uint32_t af[4][4], bq[2][4];
#pragma unroll
            for (int mi = 0; mi < 4; mi++)
                ldsm_x4(af[mi], (uint32_t)__cvta_generic_to_shared(
                            &as[swz(wm + mi * 16 + a_row, ks + a_col)]));
#pragma unroll
            for (int np = 0; np < 2; np++)
                ldsm_x4(bq[np], (uint32_t)__cvta_generic_to_shared(
                            &bs[swz(wn + np * 16 + b_row, ks + b_col)]));
#pragma unroll
            for (int mi = 0; mi < 4; mi++) {
                mma8(acc[mi][0], af[mi], &bq[0][0]);
                mma8(acc[mi][1], af[mi], &bq[0][2]);
                mma8(acc[mi][2], af[mi], &bq[1][0]);
                mma8(acc[mi][3], af[mi], &bq[1][2]);
            }
        }
        if (more) {
            stage ^= 1;
            sts8(As[stage], rowL, colL, ra0, ra1);
            sts8(Bs[stage], rowL, colL, rb0, rb1);
            __syncthreads();
        }
    }
    const int qr = lane >> 2, cb = 2 * (lane & 3);
#pragma unroll
    for (int mi = 0; mi < 4; mi++) {
        const int mm = m0 + wm + mi * 16 + qr;
#pragma unroll
        for (int ni = 0; ni < 4; ni++) {
            const int n = n0 + wn + ni * 8 + cb;
            const float b0 = bias[n], b1 = bias[n + 1];
            float* dst = Y + (size_t)mm * CD + n;
            *(float2*)dst = make_float2(acc[mi][ni][0] + b0, acc[mi][ni][1] + b1);
            *(float2*)(dst + 8 * CD) =
                make_float2(acc[mi][ni][2] + b0, acc[mi][ni][3] + b1);
        }
    }
}

// ---------------------------------------------------------------------------
extern "C" void kernel_launch(void* const* d_in, const int* in_sizes, int n_in,
                              void* d_out, int out_size) {
    const float* q  = (const float*)d_in[0];
    const float* k  = (const float*)d_in[1];
    const float* v  = (const float*)d_in[2];
    const float* wq = (const float*)d_in[3];
    const float* bq = (const float*)d_in[4];
    const float* wk = (const float*)d_in[5];
    const float* bk = (const float*)d_in[6];
    const float* wv = (const float*)d_in[7];
    const float* bv = (const float*)d_in[8];
    const float* wo = (const float*)d_in[9];
    const float* bo = (const float*)d_in[10];

    float* out  = (float*)d_out;
    float* attn = out + (size_t)CB * CS * CD;

    float *qh, *kh, *vh, *om, *gl;
    cudaGetSymbolAddress((void**)&qh, g_qh);
    cudaGetSymbolAddress((void**)&kh, g_kh);
    cudaGetSymbolAddress((void**)&vh, g_vh);
    cudaGetSymbolAddress((void**)&om, g_om);
    cudaGetSymbolAddress((void**)&gl, g_l);

    const int statsSmem = (8192 + 4096 + 256) * 4;            // 50,176 B
    const int fusedSmem = (8192 + 4096 + 4608 + 8192 + 128) * 4;  // 100,864 B
    cudaFuncSetAttribute(stats_kernel,
                         cudaFuncAttributeMaxDynamicSharedMemorySize, statsSmem);
    cudaFuncSetAttribute(fused_pv_kernel,
                         cudaFuncAttributeMaxDynamicSharedMemorySize, fusedSmem);

    const dim3 blk(256);
    qkv_proj_kernel<<<dim3(8, 32), blk>>>(q, wq, bq, qh);
    qkv_proj_kernel<<<dim3(8, 32), blk>>>(k, wk, bk, kh);
    qkv_proj_kernel<<<dim3(8, 32), blk>>>(v, wv, bv, vh);
    stats_kernel<<<dim3(16, 32), blk, statsSmem>>>(qh, kh, gl);
    fused_pv_kernel<<<dim3(16, 32), blk, fusedSmem>>>(qh, kh, vh, gl, attn, om);
    out_proj_kernel<<<dim3(8, 32), blk>>>(om, wo, bo, out);
}

// round 11
// speedup vs baseline: 1.5186x; 1.5186x over previous
#include <cuda_runtime.h>
#include <cstdint>

// Problem constants: B=2, S=2048, D=1024, H=16, dk=64
constexpr int CB  = 2;
constexpr int CS  = 2048;
constexpr int CD  = 1024;
constexpr int CH  = 16;
constexpr int CDK = 64;
constexpr int CBH = CB * CH;

// Scratch (static device globals — no allocation)
__device__ float g_qh[(size_t)CB * CH * CS * CDK];   // [z][s][dk]
__device__ float g_kh[(size_t)CB * CH * CS * CDK];
__device__ float g_vh[(size_t)CB * CH * CS * CDK];
__device__ float g_om[(size_t)CB * CS * CD];         // merged [B,S,D]
__device__ float g_l[(size_t)CBH * CS];              // row sum of exp(s/8)

__device__ __forceinline__ uint32_t f2tf(float f) {
    uint32_t u;
    asm("cvt.rna.tf32.f32 %0, %1;" : "=r"(u) : "f"(f));
    return u;
}

__device__ __forceinline__ void mma8(float* d, const uint32_t* a, const uint32_t* b) {
    asm volatile(
        "mma.sync.aligned.m16n8k8.row.col.f32.tf32.tf32.f32 "
        "{%0,%1,%2,%3}, {%4,%5,%6,%7}, {%8,%9}, {%0,%1,%2,%3};"
        : "+f"(d[0]), "+f"(d[1]), "+f"(d[2]), "+f"(d[3])
        : "r"(a[0]), "r"(a[1]), "r"(a[2]), "r"(a[3]), "r"(b[0]), "r"(b[1]));
}

__device__ __forceinline__ void ldsm_x4(uint32_t* r, uint32_t addr) {
    asm volatile("ldmatrix.sync.aligned.m8n8.x4.shared.b16 {%0,%1,%2,%3}, [%4];"
                 : "=r"(r[0]), "=r"(r[1]), "=r"(r[2]), "=r"(r[3]) : "r"(addr));
}

// Swizzled word offset inside a [rows][16-word] tile.
__device__ __forceinline__ int swz(int row, int col) {
    return row * 16 + ((((col >> 2) ^ ((row >> 1) & 3)) << 2) | (col & 3));
}

__device__ __forceinline__ void sts8(uint32_t* buf, int row, int col,
                                     float4 a, float4 b) {
    uint4 u0 = make_uint4(f2tf(a.x), f2tf(a.y), f2tf(a.z), f2tf(a.w));
    uint4 u1 = make_uint4(f2tf(b.x), f2tf(b.y), f2tf(b.z), f2tf(b.w));
    *(uint4*)&buf[swz(row, col)]     = u0;
    *(uint4*)&buf[swz(row, col + 4)] = u1;
}

// ===========================================================================
// QKV projection: 128x128 tile, BK=16, double buffered, 2 blocks/SM.
// ===========================================================================
__global__ __launch_bounds__(256, 2) void qkv_proj_kernel(
        const float* __restrict__ X, const float* __restrict__ W,
        const float* __restrict__ bias, float* __restrict__ Yh) {
    __shared__ __align__(16) uint32_t As[2][128 * 16];
    __shared__ __align__(16) uint32_t Bs[2][128 * 16];
    const int tid = threadIdx.x, lane = tid & 31, warp = tid >> 5;
    const int m0 = blockIdx.y * 128, n0 = blockIdx.x * 128;
    const int rowL = tid >> 1, colL = (tid & 1) * 8;
    const int wm = (warp >> 2) * 64, wn = (warp & 3) * 32;
    const int a_row = lane & 15,               a_col = (lane >> 4) * 4;
    const int b_row = (lane & 7) + ((lane >> 4) << 3), b_col = ((lane >> 3) & 1) * 4;

    const float* Ap = X + (size_t)(m0 + rowL) * CD + colL;
    const float* Bp = W + (size_t)(n0 + rowL) * CD + colL;

    float4 ra0 = *(const float4*)Ap, ra1 = *(const float4*)(Ap + 4);
    float4 rb0 = *(const float4*)Bp, rb1 = *(const float4*)(Bp + 4);

    float acc[4][4][4] = {};
    int stage = 0;
    sts8(As[0], rowL, colL, ra0, ra1);
    sts8(Bs[0], rowL, colL, rb0, rb1);
    __syncthreads();

    for (int k0 = 0; k0 < CD; k0 += 16) {
        const bool more = (k0 + 16 < CD);
        if (more) {
            ra0 = *(const float4*)(Ap + k0 + 16); ra1 = *(const float4*)(Ap + k0 + 20);
            rb0 = *(const float4*)(Bp + k0 + 16); rb1 = *(const float4*)(Bp + k0 + 20);
        }
        const uint32_t* as = As[stage];
        const uint32_t* bs = Bs[stage];
#pragma unroll
        for (int ks = 0; ks < 16; ks += 8) {
            uint32_t af[4][4], bq[2][4];
#pragma unroll
            for (int mi = 0; mi < 4; mi++)
                ldsm_x4(af[mi], (uint32_t)__cvta_generic_to_shared(
                            &as[swz(wm + mi * 16 + a_row, ks + a_col)]));
#pragma unroll
            for (int np = 0; np < 2; np++)
                ldsm_x4(bq[np], (uint32_t)__cvta_generic_to_shared(
                            &bs[swz(wn + np * 16 + b_row, ks + b_col)]));
#pragma unroll
            for (int mi = 0; mi < 4; mi++) {
                mma8(acc[mi][0], af[mi], &bq[0][0]);
                mma8(acc[mi][1], af[mi], &bq[0][2]);
                mma8(acc[mi][2], af[mi], &bq[1][0]);
                mma8(acc[mi][3], af[mi], &bq[1][2]);
            }
        }
        if (more) {
            stage ^= 1;
            sts8(As[stage], rowL, colL, ra0, ra1);
            sts8(Bs[stage], rowL, colL, rb0, rb1);
            __syncthreads();
        }
    }
    const int qr = lane >> 2, cb = 2 * (lane & 3);
#pragma unroll
    for (int mi = 0; mi < 4; mi++) {
        const int m  = m0 + wm + mi * 16 + qr;
        const int bb = m >> 11, ss = m & 2047;
#pragma unroll
        for (int ni = 0; ni < 4; ni++) {
            const int n = n0 + wn + ni * 8 + cb;
            const int h = n >> 6, d = n & 63;
            const float b0 = bias[n], b1 = bias[n + 1];
            float* dst = Yh + ((size_t)(bb * CH + h) * CS + ss) * CDK + d;
            *(float2*)dst = make_float2(acc[mi][ni][0] + b0, acc[mi][ni][1] + b1);
            *(float2*)(dst + 8 * CDK) =
                make_float2(acc[mi][ni][2] + b0, acc[mi][ni][3] + b1);
        }
    }
}

// ===========================================================================
// Pass 1: l[row] = sum_j exp(s_ij/8).  j-tile 64, 50KB smem, 2 blocks/SM.
// Warp layout 4m x 2n (32x32 tiles) over the 128x64 S tile.
// ===========================================================================
__global__ __launch_bounds__(256, 2) void stats_kernel(
        const float* __restrict__ qh, const float* __restrict__ kh,
        float* __restrict__ gl) {
    extern __shared__ __align__(16) uint32_t sm[];
    uint32_t* Qs = sm;                    // 4 chunks x 2048
    uint32_t* Ks = sm + 8192;             // 4 chunks x 1024
    float* redL  = (float*)(sm + 12288);  // 256

    const int tid = threadIdx.x, lane = tid & 31, warp = tid >> 5;
    const int z = blockIdx.y, m0 = blockIdx.x * 128;
    const int rowL = tid >> 1, colL = (tid & 1) * 8;
    const int krow = tid & 63, kch = tid >> 6;
    const int wm = (warp >> 1) * 32, wn = (warp & 1) * 32;
    const int a_row = lane & 15,               a_col = (lane >> 4) * 4;
    const int b_row = (lane & 7) + ((lane >> 4) << 3), b_col = ((lane >> 3) & 1) * 4;
    const int qr = lane >> 2;

    const float* Qg = qh + ((size_t)z * CS + m0) * CDK;
    const float* Kg = kh + (size_t)z * CS * CDK;

#pragma unroll
    for (int c = 0; c < 4; c++) {
        const float* s = Qg + (size_t)rowL * CDK + c * 16 + colL;
        sts8(Qs + c * 2048, rowL, colL, *(const float4*)s, *(const float4*)(s + 4));
    }
    float4 kp[4];
    {
        const float* s = Kg + (size_t)krow * CDK + kch * 16;
#pragma unroll
        for (int i = 0; i < 4; i++) kp[i] = *(const float4*)(s + i * 4);
    }
    __syncthreads();

    float lacc[2][2] = {};
    for (int jb = 0; jb < 32; jb++) {
        sts8(Ks + kch * 1024, krow, 0, kp[0], kp[1]);
        sts8(Ks + kch * 1024, krow, 8, kp[2], kp[3]);
        __syncthreads();
        if (jb < 31) {
            const float* s = Kg + (size_t)((jb + 1) * 64 + krow) * CDK + kch * 16;
#pragma unroll
            for (int i = 0; i < 4; i++) kp[i] = *(const float4*)(s + i * 4);
        }

        float acc[2][4][4] = {};
#pragma unroll
        for (int c = 0; c < 4; c++) {
            const uint32_t* as = Qs + c * 2048;
            const uint32_t* bs = Ks + c * 1024;
#pragma unroll
            for (int ks = 0; ks < 16; ks += 8) {
                uint32_t af[2][4], bq[2][4];
#pragma unroll
                for (int mi = 0; mi < 2; mi++)
                    ldsm_x4(af[mi], (uint32_t)__cvta_generic_to_shared(
                                &as[swz(wm + mi * 16 + a_row, ks + a_col)]));
#pragma unroll
                for (int np = 0; np < 2; np++)
                    ldsm_x4(bq[np], (uint32_t)__cvta_generic_to_shared(
                                &bs[swz(wn + np * 16 + b_row, ks + b_col)]));
#pragma unroll
                for (int mi = 0; mi < 2; mi++) {
                    mma8(acc[mi][0], af[mi], &bq[0][0]);
                    mma8(acc[mi][1], af[mi], &bq[0][2]);
                    mma8(acc[mi][2], af[mi], &bq[1][0]);
                    mma8(acc[mi][3], af[mi], &bq[1][2]);
                }
            }
        }
#pragma unroll
        for (int mi = 0; mi < 2; mi++)
#pragma unroll
            for (int ni = 0; ni < 4; ni++) {
                lacc[mi][0] += __expf(acc[mi][ni][0] * 0.125f) +
                               __expf(acc[mi][ni][1] * 0.125f);
                lacc[mi][1] += __expf(acc[mi][ni][2] * 0.125f) +
                               __expf(acc[mi][ni][3] * 0.125f);
            }
        __syncthreads();   // Ks reads done before next STS
    }
#pragma unroll
    for (int mi = 0; mi < 2; mi++)
#pragma unroll
        for (int h = 0; h < 2; h++) {
            float v = lacc[mi][h];
            v += __shfl_xor_sync(~0u, v, 1);
            v += __shfl_xor_sync(~0u, v, 2);
            if ((lane & 3) == 0)
                redL[(wm + mi * 16 + qr + 8 * h) * 2 + (warp & 1)] = v;
        }
    __syncthreads();
    if (tid < 128)
        gl[(size_t)z * CS + m0 + tid] = redL[tid * 2] + redL[tid * 2 + 1];
}

// ===========================================================================
// Pass 2: recompute S (128x64 tiles), write normalized attn once, O += P@V.
// ~101KB smem -> 2 blocks/SM. 2 syncs/jb; K/V prefetched under MMA.
// ===========================================================================
__global__ __launch_bounds__(256, 2) void fused_pv_kernel(
        const float* __restrict__ qh, const float* __restrict__ kh,
        const float* __restrict__ vh, const float* __restrict__ gl,
        float* __restrict__ attn, float* __restrict__ om) {
    extern __shared__ __align__(16) uint32_t sm[];
    uint32_t* Qs = sm;                    // 4 x 2048 = 8192
    uint32_t* Ks = sm + 8192;             // 4 x 1024 = 4096
    uint32_t* Vs = sm + 12288;            // 64*72    = 4608
    uint32_t* Ps = sm + 16896;            // 4 x 2048 = 8192
    float* iS = (float*)(sm + 25088);     // 128

    const int tid = threadIdx.x, lane = tid & 31, warp = tid >> 5;
    const int z = blockIdx.y, m0 = blockIdx.x * 128;
    const int rowL = tid >> 1, colL = (tid & 1) * 8;
    const int krow = tid & 63, kch = tid >> 6;
    const int vrow = tid & 63, vc0 = (tid >> 6) * 16;
    const int wm = (warp >> 1) * 32, wn = (warp & 1) * 32;
    const int a_row = lane & 15,               a_col = (lane >> 4) * 4;
    const int b_row = (lane & 7) + ((lane >> 4) << 3), b_col = ((lane >> 3) & 1) * 4;
    const int qr = lane >> 2, cb = 2 * (lane & 3);

    const float* Qg = qh + ((size_t)z * CS + m0) * CDK;
    const float* Kg = kh + (size_t)z * CS * CDK;
    const float* Vg = vh + (size_t)z * CS * CDK;
    float* Cattn = attn + (size_t)z * CS * CS;

    // Prologue: Q, K(0), V(0), iS
#pragma unroll
    for (int c = 0; c < 4; c++) {
        const float* s = Qg + (size_t)rowL * CDK + c * 16 + colL;
        sts8(Qs + c * 2048, rowL, colL, *(const float4*)s, *(const float4*)(s + 4));
    }
    {
        const float* s = Kg + (size_t)krow * CDK + kch * 16;
        sts8(Ks + kch * 1024, krow, 0, *(const float4*)s, *(const float4*)(s + 4));
        sts8(Ks + kch * 1024, krow, 8, *(const float4*)(s + 8), *(const float4*)(s + 12));
    }
    {
        const float* s = Vg + (size_t)vrow * CDK + vc0;
#pragma unroll
        for (int i = 0; i < 4; i++) {
            float4 t = *(const float4*)(s + i * 4);
            *(uint4*)&Vs[vrow * 72 + vc0 + i * 4] =
                make_uint4(f2tf(t.x), f2tf(t.y), f2tf(t.z), f2tf(t.w));
        }
    }
    if (tid < 128) iS[tid] = 1.0f / gl[(size_t)z * CS + m0 + tid];
    float acc_o[2][4][4] = {};
    __syncthreads();

    for (int jb = 0; jb < 32; jb++) {
        const int j0 = jb * 64;
        const bool more = (jb < 31);

        // Prefetch next K/V into registers (hidden under S-MMA / PV)
        float4 kp[4], vp[4];
        if (more) {
            const float* s = Kg + (size_t)(j0 + 64 + krow) * CDK + kch * 16;
#pragma unroll
            for (int i = 0; i < 4; i++) kp[i] = *(const float4*)(s + i * 4);
            const float* v = Vg + (size_t)(j0 + 64 + vrow) * CDK + vc0;
#pragma unroll
            for (int i = 0; i < 4; i++) vp[i] = *(const float4*)(v + i * 4);
        }

        // --- S = Q @ K^T (128x64), warp tile 32x32 ---
        float acc[2][4][4] = {};
#pragma unroll
        for (int c = 0; c < 4; c++) {
            const uint32_t* as = Qs + c * 2048;
            const uint32_t* bs = Ks + c * 1024;
#pragma unroll
            for (int ks = 0; ks < 16; ks += 8) {
                uint32_t af[2][4], bq[2][4];
#pragma unroll
                for (int mi = 0; mi < 2; mi++)
                    ldsm_x4(af[mi], (uint32_t)__cvta_generic_to_shared(
                                &as[swz(wm + mi * 16 + a_row, ks + a_col)]));
#pragma unroll
                for (int np = 0; np < 2; np++)
                    ldsm_x4(bq[np], (uint32_t)__cvta_generic_to_shared(
                                &bs[swz(wn + np * 16 + b_row, ks + b_col)]));
#pragma unroll
                for (int mi = 0; mi < 2; mi++) {
                    mma8(acc[mi][0], af[mi], &bq[0][0]);
                    mma8(acc[mi][1], af[mi], &bq[0][2]);
                    mma8(acc[mi][2], af[mi], &bq[1][0]);
                    mma8(acc[mi][3], af[mi], &bq[1][2]);
                }
            }
        }

        // --- P = exp(s/8)/l : streaming store attn + tf32 to Ps ---
#pragma unroll
        for (int mi = 0; mi < 2; mi++) {
            const int r0 = wm + mi * 16 + qr;
            const float i0 = iS[r0], i1 = iS[r0 + 8];
#pragma unroll
            for (int ni = 0; ni < 4; ni++) {
                const int n = wn + ni * 8 + cb;
                const float p0 = __expf(acc[mi][ni][0] * 0.125f) * i0;
                const float p1 = __expf(acc[mi][ni][1] * 0.125f) * i0;
                const float p2 = __expf(acc[mi][ni][2] * 0.125f) * i1;
                const float p3 = __expf(acc[mi][ni][3] * 0.125f) * i1;
                __stcs((float2*)(Cattn + (size_t)(m0 + r0) * CS + j0 + n),
                       make_float2(p0, p1));
                __stcs((float2*)(Cattn + (size_t)(m0 + r0 + 8) * CS + j0 + n),
                       make_float2(p2, p3));
                const int c = n >> 4, cl = n & 15;
                *(uint2*)&Ps[c * 2048 + swz(r0, cl)]     = make_uint2(f2tf(p0), f2tf(p1));
                *(uint2*)&Ps[c * 2048 + swz(r0 + 8, cl)] = make_uint2(f2tf(p2), f2tf(p3));
            }
        }
        __syncthreads();   // A: Ps visible, Ks reads done

        if (more) {
            sts8(Ks + kch * 1024, krow, 0, kp[0], kp[1]);
            sts8(Ks + kch * 1024, krow, 8, kp[2], kp[3]);
        }

        // --- O += P @ V : warp tile 32x32, K=64 ---
#pragma unroll
        for (int kslice = 0; kslice < 8; kslice++) {
            const uint32_t* as = Ps + (kslice >> 1) * 2048;
            const int ks2 = (kslice & 1) * 8;
            uint32_t af[2][4], bf[4][2];
#pragma unroll
            for (int mi = 0; mi < 2; mi++)
                ldsm_x4(af[mi], (uint32_t)__cvta_generic_to_shared(
                            &as[swz(wm + mi * 16 + a_row, ks2 + a_col)]));
            const int kf = kslice * 8 + (lane & 3);
            const int nf = wn + qr;
#pragma unroll
            for (int ni = 0; ni < 4; ni++) {
                bf[ni][0] = Vs[kf * 72 + nf + ni * 8];
                bf[ni][1] = Vs[(kf + 4) * 72 + nf + ni * 8];
            }
#pragma unroll
            for (int mi = 0; mi < 2; mi++)
#pragma unroll
                for (int ni = 0; ni < 4; ni++)
                    mma8(acc_o[mi][ni], af[mi], bf[ni]);
        }
        __syncthreads();   // B: Vs/Ps reads done, Ks STS visible

        if (more) {
#pragma unroll
            for (int i = 0; i < 4; i++)
                *(uint4*)&Vs[vrow * 72 + vc0 + i * 4] =
                    make_uint4(f2tf(vp[i].x), f2tf(vp[i].y),
                               f2tf(vp[i].z), f2tf(vp[i].w));
        }
    }
    // --- O epilogue: merged [B,S,D] ---
    const int bb = z >> 4, h = z & 15;
#pragma unroll
    for (int mi = 0; mi < 2; mi++) {
        const int m = m0 + wm + mi * 16 + qr;
#pragma unroll
        for (int ni = 0; ni < 4; ni++) {
            const int n = wn + ni * 8 + cb;
            float* dst = om + ((size_t)(bb * CS + m)) * CD + h * 64 + n;
            *(float2*)dst = make_float2(acc_o[mi][ni][0], acc_o[mi][ni][1]);
            *(float2*)(dst + 8 * CD) = make_float2(acc_o[mi][ni][2], acc_o[mi][ni][3]);
        }
    }
}

// ===========================================================================
// Output projection: out = om @ Wo^T + bo. 2 blocks/SM.
// ===========================================================================
__global__ __launch_bounds__(256, 2) void out_proj_kernel(
        const float* __restrict__ OM, const float* __restrict__ W,
        const float* __restrict__ bias, float* __restrict__ Y) {
    __shared__ __align__(16) uint32_t As[2][128 * 16];
    __shared__ __align__(16) uint32_t Bs[2][128 * 16];
    const int tid = threadIdx.x, lane = tid & 31, warp = tid >> 5;
    const int m0 = blockIdx.y * 128, n0 = blockIdx.x * 128;
    const int rowL = tid >> 1, colL = (tid & 1) * 8;
    const int wm = (warp >> 2) * 64, wn = (warp & 3) * 32;
    const int a_row = lane & 15,               a_col = (lane >> 4) * 4;
    const int b_row = (lane & 7) + ((lane >> 4) << 3), b_col = ((lane >> 3) & 1) * 4;

    const float* Ap = OM + (size_t)(m0 + rowL) * CD + colL;
    const float* Bp = W + (size_t)(n0 + rowL) * CD + colL;

    float4 ra0 = *(const float4*)Ap, ra1 = *(const float4*)(Ap + 4);
    float4 rb0 = *(const float4*)Bp, rb1 = *(const float4*)(Bp + 4);

    float acc[4][4][4] = {};
    int stage = 0;
    sts8(As[0], rowL, colL, ra0, ra1);
    sts8(Bs[0], rowL, colL, rb0, rb1);
    __syncthreads();

    for (int k0 = 0; k0 < CD; k0 += 16) {
        const bool more = (k0 + 16 < CD);
        if (more) {
            ra0 = *(const float4*)(Ap + k0 + 16); ra1 = *(const float4*)(Ap + k0 + 20);
            rb0 = *(const float4*)(Bp + k0 + 16); rb1 = *(const float4*)(Bp + k0 + 20);
        }
        const uint32_t* as = As[stage];
        const uint32_t* bs = Bs[stage];
#pragma unroll
        for (int ks = 0; ks < 16; ks += 8) {
            uint32_t af[4][4], bq[2][4];
#pragma unroll
            for (int mi = 0; mi < 4; mi++)
                ldsm_x4(af[mi], (uint32_t)__cvta_generic_to_shared(
                            &as[swz(wm + mi * 16 + a_row, ks + a_col)]));
#pragma unroll
            for (int np = 0; np < 2; np++)
                ldsm_x4(bq[np], (uint32_t)__cvta_generic_to_shared(
                            &bs[swz(wn + np * 16 + b_row, ks + b_col)]));
#pragma unroll
            for (int mi = 0; mi < 4; mi++) {
                mma8(acc[mi][0], af[mi], &bq[0][0]);
                mma8(acc[mi][1], af[mi], &bq[0][2]);
                mma8(acc[mi][2], af[mi], &bq[1][0]);
                mma8(acc[mi][3], af[mi], &bq[1][2]);
            }
        }
        if (more) {
            stage ^= 1;
            sts8(As[stage], rowL, colL, ra0, ra1);
            sts8(Bs[stage], rowL, colL, rb0, rb1);
            __syncthreads();
        }
    }
    const int qr = lane >> 2, cb = 2 * (lane & 3);
#pragma unroll
    for (int mi = 0; mi < 4; mi++) {
        const int mm = m0 + wm + mi * 16 + qr;
#pragma unroll
        for (int ni = 0; ni < 4; ni++) {
            const int n = n0 + wn + ni * 8 + cb;
            const float b0 = bias[n], b1 = bias[n + 1];
            float* dst = Y + (size_t)mm * CD + n;
            *(float2*)dst = make_float2(acc[mi][ni][0] + b0, acc[mi][ni][1] + b1);
            *(float2*)(dst + 8 * CD) =
                make_float2(acc[mi][ni][2] + b0, acc[mi][ni][3] + b1);
        }
    }
}

// ---------------------------------------------------------------------------
extern "C" void kernel_launch(void* const* d_in, const int* in_sizes, int n_in,
                              void* d_out, int out_size) {
    const float* q  = (const float*)d_in[0];
    const float* k  = (const float*)d_in[1];
    const float* v  = (const float*)d_in[2];
    const float* wq = (const float*)d_in[3];
    const float* bq = (const float*)d_in[4];
    const float* wk = (const float*)d_in[5];
    const float* bk = (const float*)d_in[6];
    const float* wv = (const float*)d_in[7];
    const float* bv = (const float*)d_in[8];
    const float* wo = (const float*)d_in[9];
    const float* bo = (const float*)d_in[10];

    float* out  = (float*)d_out;
    float* attn = out + (size_t)CB * CS * CD;

    float *qh, *kh, *vh, *om, *gl;
    cudaGetSymbolAddress((void**)&qh, g_qh);
    cudaGetSymbolAddress((void**)&kh, g_kh);
    cudaGetSymbolAddress((void**)&vh, g_vh);
    cudaGetSymbolAddress((void**)&om, g_om);
    cudaGetSymbolAddress((void**)&gl, g_l);

    const int statsSmem = (8192 + 4096 + 256) * 4;            // 50,176 B
    const int fusedSmem = (8192 + 4096 + 4608 + 8192 + 128) * 4;  // 100,864 B
    cudaFuncSetAttribute(stats_kernel,
                         cudaFuncAttributeMaxDynamicSharedMemorySize, statsSmem);
    cudaFuncSetAttribute(fused_pv_kernel,
                         cudaFuncAttributeMaxDynamicSharedMemorySize, fusedSmem);

    const dim3 blk(256);
    qkv_proj_kernel<<<dim3(8, 32), blk>>>(q, wq, bq, qh);
    qkv_proj_kernel<<<dim3(8, 32), blk>>>(k, wk, bk, kh);
    qkv_proj_kernel<<<dim3(8, 32), blk>>>(v, wv, bv, vh);
    stats_kernel<<<dim3(16, 32), blk, statsSmem>>>(qh, kh, gl);
    fused_pv_kernel<<<dim3(16, 32), blk, fusedSmem>>>(qh, kh, vh, gl, attn, om);
    out_proj_kernel<<<dim3(8, 32), blk>>>(om, wo, bo, out);
}